// round 6
// baseline (speedup 1.0000x reference)
#include <cuda_runtime.h>
#include <cstdint>

// SubjectLayer: 256 SGEMMs (M=256, K=256, N=3000), tf32 mma.sync m16n8k8.
// CTA: full M=256 x N-tile 128. 8 warps, warp tile 64x64. 3-stage cp.async.
//   x:[256,256,1,3000] f32, weight:[128,256,256] f32, bias:[128,256] f32,
//   subj:[256] int32, out:[256,256,1,3000] f32

#define NSP 3000
#define CIN 256
#define TM 256
#define TN 128
#define TK 32
#define NCHUNK 8
#define NSTAGE 3

#define AS_STRIDE 36                   // 32 + pad -> conflict-free frag LDS
#define BS_STRIDE 136                  // 128 + pad
#define AS_TILE (TM * AS_STRIDE)       // 9216 floats
#define BS_TILE (TK * BS_STRIDE)       // 4352 floats
#define STAGE_FLOATS (AS_TILE + BS_TILE)
#define SMEM_BYTES (NSTAGE * STAGE_FLOATS * 4)   // 162816

__device__ __forceinline__ uint32_t f2tf32(float f) {
    uint32_t r;
    asm("cvt.rna.tf32.f32 %0, %1;" : "=r"(r) : "f"(f));
    return r;
}
__device__ __forceinline__ void cp16(uint32_t dst, const void* src) {
    asm volatile("cp.async.cg.shared.global [%0], [%1], 16;\n" :: "r"(dst), "l"(src));
}
__device__ __forceinline__ void cp16z(uint32_t dst, const void* src, int src_size) {
    asm volatile("cp.async.cg.shared.global [%0], [%1], 16, %2;\n"
                 :: "r"(dst), "l"(src), "r"(src_size));
}
__device__ __forceinline__ void mma_tf32(float* d, const uint32_t* a,
                                         uint32_t b0, uint32_t b1) {
    asm volatile(
        "mma.sync.aligned.m16n8k8.row.col.f32.tf32.tf32.f32 "
        "{%0,%1,%2,%3}, {%4,%5,%6,%7}, {%8,%9}, {%0,%1,%2,%3};\n"
        : "+f"(d[0]), "+f"(d[1]), "+f"(d[2]), "+f"(d[3])
        : "r"(a[0]), "r"(a[1]), "r"(a[2]), "r"(a[3]), "r"(b0), "r"(b1));
}

extern __shared__ float smem[];

__global__ __launch_bounds__(256, 1)
void subject_tf32_kernel(const float* __restrict__ x,
                         const float* __restrict__ weight,
                         const float* __restrict__ bias,
                         const int* __restrict__ subj,
                         float* __restrict__ out)
{
    const int b  = blockIdx.z;
    const int n0 = blockIdx.x * TN;

    const int s = subj[b];
    const float* __restrict__ Wm = weight + (size_t)s * CIN * CIN;   // [256,256]
    const float* __restrict__ X  = x      + (size_t)b * CIN * NSP;   // [256,3000]
    const float* __restrict__ Bv = bias   + (size_t)s * CIN;
    float* __restrict__ O        = out    + (size_t)b * CIN * NSP;

    const uint32_t smem_u32 = (uint32_t)__cvta_generic_to_shared(smem);

    const int tid    = threadIdx.x;
    const int wid    = tid >> 5;
    const int lane   = tid & 31;
    const int warp_m = wid & 3;        // 0..3 -> 64-row slabs
    const int warp_n = wid >> 2;       // 0..1 -> 64-col slabs
    const int group  = lane >> 2;      // 0..7
    const int tig    = lane & 3;       // 0..3

    const int am = warp_m * 64;
    const int bn = warp_n * 64;

    float acc[4][8][4];
    #pragma unroll
    for (int mi = 0; mi < 4; mi++)
        #pragma unroll
        for (int ni = 0; ni < 8; ni++)
            #pragma unroll
            for (int r = 0; r < 4; r++)
                acc[mi][ni][r] = 0.0f;

    // Per-thread load coords.
    // A: 256x32 f = 2048 float4, 8/thread.  B: 32x128 f = 1024 float4, 4/thread.
    const int a_k4 = (tid & 7) << 2;      // (idx%8)*4
    const int b_n4 = (tid & 31) << 2;     // (idx%32)*4

    auto load_chunk = [&](int stage, int c) {
        const int k0 = c * TK;
        uint32_t abase = smem_u32 + (uint32_t)(stage * STAGE_FLOATS) * 4;
        uint32_t bbase = abase + (uint32_t)AS_TILE * 4;
        #pragma unroll
        for (int i = 0; i < 8; i++) {
            int m = (i * 256 + tid) >> 3;                  // 0..255
            cp16(abase + (uint32_t)(m * AS_STRIDE + a_k4) * 4,
                 Wm + (size_t)m * CIN + k0 + a_k4);
        }
        #pragma unroll
        for (int i = 0; i < 4; i++) {
            int k = (i * 256 + tid) >> 5;                  // 0..31
            int n = n0 + b_n4;
            int ok = (n < NSP);
            cp16z(bbase + (uint32_t)(k * BS_STRIDE + b_n4) * 4,
                  X + (size_t)(k0 + k) * NSP + (ok ? n : 0),
                  ok ? 16 : 0);
        }
        asm volatile("cp.async.commit_group;\n");
    };

    auto compute_chunk = [&](int stage) {
        const float* A = smem + stage * STAGE_FLOATS;
        const float* B = A + AS_TILE;
        #pragma unroll
        for (int kk = 0; kk < 4; kk++) {
            const int k8 = kk * 8;
            uint32_t af[4][4];
            #pragma unroll
            for (int mi = 0; mi < 4; mi++) {
                const int r = am + mi * 16;
                af[mi][0] = f2tf32(A[(r + group)     * AS_STRIDE + k8 + tig]);
                af[mi][1] = f2tf32(A[(r + group + 8) * AS_STRIDE + k8 + tig]);
                af[mi][2] = f2tf32(A[(r + group)     * AS_STRIDE + k8 + tig + 4]);
                af[mi][3] = f2tf32(A[(r + group + 8) * AS_STRIDE + k8 + tig + 4]);
            }
            #pragma unroll
            for (int ni = 0; ni < 8; ni++) {
                uint32_t b0 = f2tf32(B[(k8 + tig)     * BS_STRIDE + bn + ni * 8 + group]);
                uint32_t b1 = f2tf32(B[(k8 + tig + 4) * BS_STRIDE + bn + ni * 8 + group]);
                #pragma unroll
                for (int mi = 0; mi < 4; mi++)
                    mma_tf32(acc[mi][ni], af[mi], b0, b1);
            }
        }
    };

    // 3-stage pipeline.
    load_chunk(0, 0);
    load_chunk(1, 1);

    #pragma unroll 1
    for (int c = 0; c < NCHUNK; c++) {
        if (c + 2 < NCHUNK) {
            load_chunk((c + 2) % NSTAGE, c + 2);
            asm volatile("cp.async.wait_group 2;\n");
        } else if (c + 1 < NCHUNK) {
            asm volatile("cp.async.wait_group 1;\n");
        } else {
            asm volatile("cp.async.wait_group 0;\n");
        }
        __syncthreads();
        compute_chunk(c % NSTAGE);
        __syncthreads();
    }

    // Epilogue: bias add + float2 stores.
    #pragma unroll
    for (int mi = 0; mi < 4; mi++) {
        const int mrow = am + mi * 16 + group;
        const float bv0 = Bv[mrow];
        const float bv1 = Bv[mrow + 8];
        #pragma unroll
        for (int ni = 0; ni < 8; ni++) {
            const int n = n0 + bn + ni * 8 + tig * 2;
            if (n < NSP) {
                float2 v0 = make_float2(acc[mi][ni][0] + bv0, acc[mi][ni][1] + bv0);
                *reinterpret_cast<float2*>(&O[(size_t)mrow * NSP + n]) = v0;
                float2 v1 = make_float2(acc[mi][ni][2] + bv1, acc[mi][ni][3] + bv1);
                *reinterpret_cast<float2*>(&O[(size_t)(mrow + 8) * NSP + n]) = v1;
            }
        }
    }
}

extern "C" void kernel_launch(void* const* d_in, const int* in_sizes, int n_in,
                              void* d_out, int out_size) {
    const float* x      = (const float*)d_in[0];
    const float* weight = (const float*)d_in[1];
    const float* bias   = (const float*)d_in[2];
    const int*   subj   = (const int*)d_in[3];
    float*       out    = (float*)d_out;

    cudaFuncSetAttribute(subject_tf32_kernel,
                         cudaFuncAttributeMaxDynamicSharedMemorySize, SMEM_BYTES);

    dim3 block(256);
    dim3 grid((NSP + TN - 1) / TN, 1, 256);   // (24, 1, 256)
    subject_tf32_kernel<<<grid, block, SMEM_BYTES>>>(x, weight, bias, subj, out);
}

// round 7
// speedup vs baseline: 1.0247x; 1.0247x over previous
#include <cuda_runtime.h>
#include <cstdint>

// SubjectLayer: 256 SGEMMs (M=256,K=256,N=3000), tf32 mma.sync m16n8k8.
// R7: hoist tf32 CVTs out of the mainloop.
//  - weight pre-converted to tf32 once per launch into __device__ g_wtf32
//  - B (x) tile converted in-place in smem once per chunk
// Main GEMM: R4 topology (CTA 128x128, 8 warps 32x64, 2-stage cp.async, 2 CTA/SM).

#define NSP 3000
#define CIN 256
#define NSUBJ 128
#define TM 128
#define TN 128
#define TK 32
#define NCHUNK 8

#define AS_STRIDE 36
#define BS_STRIDE 136
#define AS_TILE (TM * AS_STRIDE)          // 4608 words
#define BS_TILE (TK * BS_STRIDE)          // 4352 words
#define SMEM_WORDS (2 * AS_TILE + 2 * BS_TILE)
#define SMEM_BYTES (SMEM_WORDS * 4)       // 71680

__device__ uint32_t g_wtf32[NSUBJ * CIN * CIN];   // 33.5 MB scratch (tf32 weights)

__device__ __forceinline__ uint32_t f2tf32(float f) {
    uint32_t r;
    asm("cvt.rna.tf32.f32 %0, %1;" : "=r"(r) : "f"(f));
    return r;
}
__device__ __forceinline__ void cp16(uint32_t dst, const void* src) {
    asm volatile("cp.async.cg.shared.global [%0], [%1], 16;\n" :: "r"(dst), "l"(src));
}
__device__ __forceinline__ void cp16z(uint32_t dst, const void* src, int src_size) {
    asm volatile("cp.async.cg.shared.global [%0], [%1], 16, %2;\n"
                 :: "r"(dst), "l"(src), "r"(src_size));
}
__device__ __forceinline__ void mma_tf32(float* d, const uint32_t* a,
                                         uint32_t b0, uint32_t b1) {
    asm volatile(
        "mma.sync.aligned.m16n8k8.row.col.f32.tf32.tf32.f32 "
        "{%0,%1,%2,%3}, {%4,%5,%6,%7}, {%8,%9}, {%0,%1,%2,%3};\n"
        : "+f"(d[0]), "+f"(d[1]), "+f"(d[2]), "+f"(d[3])
        : "r"(a[0]), "r"(a[1]), "r"(a[2]), "r"(a[3]), "r"(b0), "r"(b1));
}

// ---- Kernel 1: weight f32 -> tf32 (once per launch) ----
__global__ __launch_bounds__(256)
void wconv_kernel(const float* __restrict__ w) {
    size_t i = ((size_t)blockIdx.x * 256 + threadIdx.x) * 4;
    float4 v = *reinterpret_cast<const float4*>(w + i);
    uint4 r;
    r.x = f2tf32(v.x); r.y = f2tf32(v.y);
    r.z = f2tf32(v.z); r.w = f2tf32(v.w);
    *reinterpret_cast<uint4*>(g_wtf32 + i) = r;
}

// ---- Kernel 2: main GEMM ----
extern __shared__ uint32_t smem[];

__global__ __launch_bounds__(256, 2)
void subject_tf32_kernel(const float* __restrict__ x,
                         const float* __restrict__ bias,
                         const int* __restrict__ subj,
                         float* __restrict__ out)
{
    const int b  = blockIdx.z;
    const int m0 = blockIdx.y * TM;
    const int n0 = blockIdx.x * TN;

    const int s = subj[b];
    const uint32_t* __restrict__ Wm = g_wtf32 + (size_t)s * CIN * CIN;  // [256,256] tf32
    const float* __restrict__ X  = x    + (size_t)b * CIN * NSP;        // [256,3000]
    const float* __restrict__ Bv = bias + (size_t)s * CIN;
    float* __restrict__ O        = out  + (size_t)b * CIN * NSP;

    uint32_t* As = smem;                        // [2][128][36] tf32
    float*    Bs = (float*)(smem + 2 * AS_TILE);// [2][32][136] f32 -> tf32 in place
    const uint32_t as_u32 = (uint32_t)__cvta_generic_to_shared(As);
    const uint32_t bs_u32 = (uint32_t)__cvta_generic_to_shared(Bs);

    const int tid    = threadIdx.x;
    const int wid    = tid >> 5;
    const int lane   = tid & 31;
    const int warp_m = wid & 3;
    const int warp_n = wid >> 2;
    const int group  = lane >> 2;
    const int tig    = lane & 3;

    const int am = warp_m * 32;
    const int bn = warp_n * 64;

    float acc[2][8][4];
    #pragma unroll
    for (int mi = 0; mi < 2; mi++)
        #pragma unroll
        for (int ni = 0; ni < 8; ni++)
            #pragma unroll
            for (int r = 0; r < 4; r++)
                acc[mi][ni][r] = 0.0f;

    const int a_m  = tid >> 3;
    const int a_k4 = (tid & 7) << 2;
    const int b_k  = tid >> 5;
    const int b_n4 = (tid & 31) << 2;
    const int gb_n = n0 + b_n4;
    const int b_ok = (gb_n < NSP);

    auto load_chunk = [&](int buf, int c) {
        const int k0 = c * TK;
        uint32_t abase = as_u32 + (uint32_t)buf * AS_TILE * 4;
        uint32_t bbase = bs_u32 + (uint32_t)buf * BS_TILE * 4;
        #pragma unroll
        for (int j = 0; j < 4; j++) {
            int m = a_m + j * 32;
            cp16(abase + (uint32_t)(m * AS_STRIDE + a_k4) * 4,
                 Wm + (size_t)(m0 + m) * CIN + k0 + a_k4);
        }
        #pragma unroll
        for (int j = 0; j < 4; j++) {
            int k = b_k + j * 8;
            cp16z(bbase + (uint32_t)(k * BS_STRIDE + b_n4) * 4,
                  X + (size_t)(k0 + k) * NSP + (b_ok ? gb_n : 0),
                  b_ok ? 16 : 0);
        }
        asm volatile("cp.async.commit_group;\n");
    };

    // In-place f32 -> tf32 of one B buffer (each thread converts what it loaded).
    auto convert_B = [&](int buf) {
        float* Bb = Bs + buf * BS_TILE;
        #pragma unroll
        for (int j = 0; j < 4; j++) {
            int k = b_k + j * 8;
            float4 v = *reinterpret_cast<float4*>(&Bb[k * BS_STRIDE + b_n4]);
            uint4 u;
            u.x = f2tf32(v.x); u.y = f2tf32(v.y);
            u.z = f2tf32(v.z); u.w = f2tf32(v.w);
            *reinterpret_cast<uint4*>(&Bb[k * BS_STRIDE + b_n4]) = u;
        }
    };

    auto compute_chunk = [&](int buf) {
        const uint32_t* A = As + buf * AS_TILE;
        const uint32_t* B = (const uint32_t*)(Bs + buf * BS_TILE);
        #pragma unroll
        for (int kk = 0; kk < 4; kk++) {
            const int k8 = kk * 8;
            uint32_t af[2][4];
            #pragma unroll
            for (int mi = 0; mi < 2; mi++) {
                const int r = am + mi * 16;
                af[mi][0] = A[(r + group)     * AS_STRIDE + k8 + tig];
                af[mi][1] = A[(r + group + 8) * AS_STRIDE + k8 + tig];
                af[mi][2] = A[(r + group)     * AS_STRIDE + k8 + tig + 4];
                af[mi][3] = A[(r + group + 8) * AS_STRIDE + k8 + tig + 4];
            }
            #pragma unroll
            for (int ni = 0; ni < 8; ni++) {
                uint32_t b0 = B[(k8 + tig)     * BS_STRIDE + bn + ni * 8 + group];
                uint32_t b1 = B[(k8 + tig + 4) * BS_STRIDE + bn + ni * 8 + group];
                mma_tf32(acc[0][ni], af[0], b0, b1);
                mma_tf32(acc[1][ni], af[1], b0, b1);
            }
        }
    };

    // Prologue: stage chunk 0, convert its B.
    load_chunk(0, 0);
    asm volatile("cp.async.wait_group 0;\n");
    __syncthreads();
    convert_B(0);
    __syncthreads();

    #pragma unroll 1
    for (int c = 0; c < NCHUNK; c++) {
        const int buf = c & 1;
        if (c + 1 < NCHUNK) load_chunk(buf ^ 1, c + 1);   // overlaps compute below
        compute_chunk(buf);
        if (c + 1 < NCHUNK) {
            asm volatile("cp.async.wait_group 0;\n");
            __syncthreads();          // all copies of chunk c+1 landed
            convert_B(buf ^ 1);
            __syncthreads();          // converted tile visible to all warps
        }
    }

    // Epilogue: bias add + float2 stores.
    #pragma unroll
    for (int mi = 0; mi < 2; mi++) {
        const int mrow = m0 + am + mi * 16 + group;
        const float bv0 = Bv[mrow];
        const float bv1 = Bv[mrow + 8];
        #pragma unroll
        for (int ni = 0; ni < 8; ni++) {
            const int n = n0 + bn + ni * 8 + tig * 2;
            if (n < NSP) {
                float2 v0 = make_float2(acc[0][ni][0] * 0.0f + acc[mi][ni][0] + bv0,
                                        acc[mi][ni][1] + bv0);
                v0.x = acc[mi][ni][0] + bv0;   // keep simple form
                *reinterpret_cast<float2*>(&O[(size_t)mrow * NSP + n]) = v0;
                float2 v1 = make_float2(acc[mi][ni][2] + bv1, acc[mi][ni][3] + bv1);
                *reinterpret_cast<float2*>(&O[(size_t)(mrow + 8) * NSP + n]) = v1;
            }
        }
    }
}

extern "C" void kernel_launch(void* const* d_in, const int* in_sizes, int n_in,
                              void* d_out, int out_size) {
    const float* x      = (const float*)d_in[0];
    const float* weight = (const float*)d_in[1];
    const float* bias   = (const float*)d_in[2];
    const int*   subj   = (const int*)d_in[3];
    float*       out    = (float*)d_out;

    // 1) weight -> tf32 scratch (8.4M elems, 4/thread)
    wconv_kernel<<<NSUBJ * CIN * CIN / (256 * 4), 256>>>(weight);

    // 2) main GEMM
    cudaFuncSetAttribute(subject_tf32_kernel,
                         cudaFuncAttributeMaxDynamicSharedMemorySize, SMEM_BYTES);
    dim3 block(256);
    dim3 grid((NSP + TN - 1) / TN, CIN / TM, 256);   // (24, 2, 256)
    subject_tf32_kernel<<<grid, block, SMEM_BYTES>>>(x, bias, subj, out);
}

// round 8
// speedup vs baseline: 1.2912x; 1.2601x over previous
#include <cuda_runtime.h>
#include <cstdint>

// SubjectLayer: 256 SGEMMs (M=256,K=256,N=3000), tf32 mma.sync m16n8k8.
// R8: fragment-ordered tf32 weight scratch (LDS.128 A frags), raw-f32 B operand
// (tf32 HW truncation), 1 sync/chunk, double-buffered B fragments.

#define NSP 3000
#define CIN 256
#define NSUBJ 128
#define TM 128
#define TN 128
#define TK 32
#define NCHUNK 8

#define A_WORDS 4096                    // 128x32 tf32, fragment-ordered, per buffer
#define BS_STRIDE 136
#define B_WORDS (TK * BS_STRIDE)        // 4352
#define SMEM_WORDS (2 * (A_WORDS + B_WORDS))
#define SMEM_BYTES (SMEM_WORDS * 4)     // 67584

// Fragment-ordered weights: W[s][c(8)][mt(16)][kk(4)][lane(32)][r(4)]
//   r order: (g,t), (g+8,t), (g,t+4), (g+8,t+4);  g=lane>>2, t=lane&3
//   m = mt*16 + g + (r&1)*8 ;  k = c*32 + kk*8 + t + (r>>1)*4
__device__ uint32_t g_wfrag[NSUBJ * CIN * CIN];

__device__ __forceinline__ uint32_t f2tf32(float f) {
    uint32_t r;
    asm("cvt.rna.tf32.f32 %0, %1;" : "=r"(r) : "f"(f));
    return r;
}
__device__ __forceinline__ void cp16(uint32_t dst, const void* src) {
    asm volatile("cp.async.cg.shared.global [%0], [%1], 16;\n" :: "r"(dst), "l"(src));
}
__device__ __forceinline__ void cp16z(uint32_t dst, const void* src, int src_size) {
    asm volatile("cp.async.cg.shared.global [%0], [%1], 16, %2;\n"
                 :: "r"(dst), "l"(src), "r"(src_size));
}
__device__ __forceinline__ void mma_tf32(float* d, const uint4 a,
                                         uint32_t b0, uint32_t b1) {
    asm volatile(
        "mma.sync.aligned.m16n8k8.row.col.f32.tf32.tf32.f32 "
        "{%0,%1,%2,%3}, {%4,%5,%6,%7}, {%8,%9}, {%0,%1,%2,%3};\n"
        : "+f"(d[0]), "+f"(d[1]), "+f"(d[2]), "+f"(d[3])
        : "r"(a.x), "r"(a.y), "r"(a.z), "r"(a.w), "r"(b0), "r"(b1));
}

// ---- Prologue: weights f32 -> tf32, permuted to fragment order ----
__global__ __launch_bounds__(256)
void wfrag_kernel(const float* __restrict__ w) {
    const int idx  = blockIdx.x * 256 + threadIdx.x;     // one uint4 per thread
    const int lane = idx & 31;
    const int kk   = (idx >> 5) & 3;
    const int mt   = (idx >> 7) & 15;
    const int c    = (idx >> 11) & 7;
    const int s    = idx >> 14;
    const int g = lane >> 2, t = lane & 3;
    const int m = mt * 16 + g;
    const int k = c * 32 + kk * 8 + t;
    const float* ws = w + (size_t)s * CIN * CIN;
    uint4 r;
    r.x = f2tf32(ws[(size_t)m       * CIN + k]);
    r.y = f2tf32(ws[(size_t)(m + 8) * CIN + k]);
    r.z = f2tf32(ws[(size_t)m       * CIN + k + 4]);
    r.w = f2tf32(ws[(size_t)(m + 8) * CIN + k + 4]);
    *reinterpret_cast<uint4*>(g_wfrag + (size_t)idx * 4) = r;
}

// ---- Main GEMM ----
extern __shared__ uint32_t smem[];

__global__ __launch_bounds__(256, 2)
void subject_tf32_kernel(const float* __restrict__ x,
                         const float* __restrict__ bias,
                         const int* __restrict__ subj,
                         float* __restrict__ out)
{
    const int b  = blockIdx.z;
    const int m0 = blockIdx.y * TM;
    const int n0 = blockIdx.x * TN;

    const int s = subj[b];
    const float* __restrict__ X  = x    + (size_t)b * CIN * NSP;    // [256,3000]
    const float* __restrict__ Bv = bias + (size_t)s * CIN;
    float* __restrict__ O        = out  + (size_t)b * CIN * NSP;

    // Chunk-c A block: 4096 contiguous words at ((s*8+c)*16 + m0/16)*512
    const size_t wbase = ((size_t)s * 8) * 16 + (m0 >> 4);

    uint32_t* As = smem;                       // [2][4096]
    uint32_t* Bs = smem + 2 * A_WORDS;         // [2][32][136] raw f32 bits
    const uint32_t as_u32 = (uint32_t)__cvta_generic_to_shared(As);
    const uint32_t bs_u32 = (uint32_t)__cvta_generic_to_shared(Bs);

    const int tid    = threadIdx.x;
    const int wid    = tid >> 5;
    const int lane   = tid & 31;
    const int warp_m = wid & 3;
    const int warp_n = wid >> 2;
    const int group  = lane >> 2;
    const int tig    = lane & 3;

    const int bn = warp_n * 64;

    float acc[2][8][4];
    #pragma unroll
    for (int mi = 0; mi < 2; mi++)
        #pragma unroll
        for (int ni = 0; ni < 8; ni++)
            #pragma unroll
            for (int r = 0; r < 4; r++)
                acc[mi][ni][r] = 0.0f;

    const int b_k  = tid >> 5;
    const int b_n4 = (tid & 31) << 2;
    const int gb_n = n0 + b_n4;
    const int b_ok = (gb_n < NSP);

    auto load_chunk = [&](int buf, int c) {
        // A: 16KB contiguous fragment block
        const uint32_t* srcA = g_wfrag + (wbase + (size_t)c * 16) * 512;
        uint32_t abase = as_u32 + (uint32_t)buf * A_WORDS * 4;
        #pragma unroll
        for (int j = 0; j < 4; j++) {
            int u = j * 256 + tid;
            cp16(abase + (uint32_t)u * 16, srcA + (size_t)u * 4);
        }
        // B: [32][128] f32, coalesced rows
        const int k0 = c * TK;
        uint32_t bbase = bs_u32 + (uint32_t)buf * B_WORDS * 4;
        #pragma unroll
        for (int j = 0; j < 4; j++) {
            int k = b_k + j * 8;
            cp16z(bbase + (uint32_t)(k * BS_STRIDE + b_n4) * 4,
                  X + (size_t)(k0 + k) * NSP + (b_ok ? gb_n : 0),
                  b_ok ? 16 : 0);
        }
        asm volatile("cp.async.commit_group;\n");
    };

    auto compute_chunk = [&](int buf) {
        const uint32_t* A = As + buf * A_WORDS;
        const uint32_t* B = Bs + buf * B_WORDS;
        // B fragment addresses for a given kk: (kk*8+tig)*136 + bn+ni*8+group
        uint32_t bw[2][16];
        auto load_bfrags = [&](uint32_t* d, int kk) {
            const int r0 = (kk * 8 + tig) * BS_STRIDE + bn + group;
            const int r1 = r0 + 4 * BS_STRIDE;
            #pragma unroll
            for (int ni = 0; ni < 8; ni++) {
                d[ni * 2]     = B[r0 + ni * 8];
                d[ni * 2 + 1] = B[r1 + ni * 8];
            }
        };
        load_bfrags(bw[0], 0);
        #pragma unroll
        for (int kk = 0; kk < 4; kk++) {
            if (kk < 3) load_bfrags(bw[(kk + 1) & 1], kk + 1);
            const uint32_t* bcur = bw[kk & 1];
            // A fragments: one LDS.128 per m-tile
            const int mtl = warp_m * 2;
            uint4 a0 = *reinterpret_cast<const uint4*>(
                &A[((mtl)     * 4 + kk) * 128 + lane * 4]);
            uint4 a1 = *reinterpret_cast<const uint4*>(
                &A[((mtl + 1) * 4 + kk) * 128 + lane * 4]);
            #pragma unroll
            for (int ni = 0; ni < 8; ni++) {
                mma_tf32(acc[0][ni], a0, bcur[ni * 2], bcur[ni * 2 + 1]);
                mma_tf32(acc[1][ni], a1, bcur[ni * 2], bcur[ni * 2 + 1]);
            }
        }
    };

    // Prologue: stage chunk 0.
    load_chunk(0, 0);
    asm volatile("cp.async.wait_group 0;\n");
    __syncthreads();

    #pragma unroll 1
    for (int c = 0; c < NCHUNK; c++) {
        const int buf = c & 1;
        if (c + 1 < NCHUNK) {
            load_chunk(buf ^ 1, c + 1);        // overlaps compute below
            compute_chunk(buf);
            asm volatile("cp.async.wait_group 0;\n");
            __syncthreads();                   // single barrier per chunk
        } else {
            compute_chunk(buf);
        }
    }

    // Epilogue: bias add + float2 stores.
    const int am = warp_m * 32;
    #pragma unroll
    for (int mi = 0; mi < 2; mi++) {
        const int mrow = m0 + am + mi * 16 + group;
        const float bv0 = Bv[mrow];
        const float bv1 = Bv[mrow + 8];
        #pragma unroll
        for (int ni = 0; ni < 8; ni++) {
            const int n = n0 + bn + ni * 8 + tig * 2;
            if (n < NSP) {
                float2 v0 = make_float2(acc[mi][ni][0] + bv0, acc[mi][ni][1] + bv0);
                *reinterpret_cast<float2*>(&O[(size_t)mrow * NSP + n]) = v0;
                float2 v1 = make_float2(acc[mi][ni][2] + bv1, acc[mi][ni][3] + bv1);
                *reinterpret_cast<float2*>(&O[(size_t)(mrow + 8) * NSP + n]) = v1;
            }
        }
    }
}

extern "C" void kernel_launch(void* const* d_in, const int* in_sizes, int n_in,
                              void* d_out, int out_size) {
    const float* x      = (const float*)d_in[0];
    const float* weight = (const float*)d_in[1];
    const float* bias   = (const float*)d_in[2];
    const int*   subj   = (const int*)d_in[3];
    float*       out    = (float*)d_out;

    // 1) weights -> tf32 fragment-ordered scratch (2.1M uint4)
    wfrag_kernel<<<NSUBJ * CIN * CIN / 4 / 256, 256>>>(weight);

    // 2) main GEMM
    cudaFuncSetAttribute(subject_tf32_kernel,
                         cudaFuncAttributeMaxDynamicSharedMemorySize, SMEM_BYTES);
    dim3 block(256);
    dim3 grid((NSP + TN - 1) / TN, CIN / TM, 256);   // (24, 2, 256)
    subject_tf32_kernel<<<grid, block, SMEM_BYTES>>>(x, bias, subj, out);
}